// round 8
// baseline (speedup 1.0000x reference)
#include <cuda_runtime.h>
#include <cstdint>

// Problem: inputs [8,128,128,64] f32, beta [64,16] f32
// out[e, c] = inputs[e] * u[e%64, c],  u = beta^2 / rowsum(beta^2)
// out flat: n4 = 2^25 float4s.
//
// R8: compute tiles into SMEM, stream them out with cp.async.bulk
// (shared->global, async proxy). Double-buffered: TMA drains tile t while
// threads fill tile t+1. The 512 MiB write stream never touches per-thread STG.

#define D_DIM 64
#define BLOCKS 1024
#define THREADS 256
#define CHUNK 32768u                 // float4s per block (2^25 / 1024) = 512 KiB
#define TILE 1024                    // float4s per tile = 16 KiB
#define TILES_PER_BLOCK (CHUNK / TILE)   // 32
#define F4_PER_THREAD (TILE / THREADS)   // 4

__device__ __forceinline__ uint32_t smem_u32(const void* p) {
    uint32_t a;
    asm("{ .reg .u64 t; cvta.to.shared.u64 t, %1; cvt.u32.u64 %0, t; }"
        : "=r"(a) : "l"(p));
    return a;
}

__global__ void __launch_bounds__(THREADS, 7) fused_broadcast_mul_tma(
    const float* __restrict__ in, const float* __restrict__ beta,
    float4* __restrict__ out) {
    __shared__ __align__(16) float4 buf[2][TILE];   // 32 KiB

    const unsigned int tid = threadIdx.x;
    const unsigned int i = tid >> 2;          // beta row (0..63)
    const unsigned int j = tid & 3u;          // float4 quarter of the row

    // ---- one-time prologue: this thread's u quarter, in registers ----
    const float4* br = reinterpret_cast<const float4*>(beta) + i * 4;
    float4 q0 = __ldg(br + 0);
    float4 q1 = __ldg(br + 1);
    float4 q2 = __ldg(br + 2);
    float4 q3 = __ldg(br + 3);
    float s = q0.x * q0.x + q0.y * q0.y + q0.z * q0.z + q0.w * q0.w
            + q1.x * q1.x + q1.y * q1.y + q1.z * q1.z + q1.w * q1.w
            + q2.x * q2.x + q2.y * q2.y + q2.z * q2.z + q2.w * q2.w
            + q3.x * q3.x + q3.y * q3.y + q3.z * q3.z + q3.w * q3.w;
    float inv = 1.0f / s;
    float4 bq = (j == 0) ? q0 : (j == 1) ? q1 : (j == 2) ? q2 : q3;
    const float4 u = make_float4(bq.x * bq.x * inv, bq.y * bq.y * inv,
                                 bq.z * bq.z * inv, bq.w * bq.w * inv);

    const unsigned int chunk_base = blockIdx.x * CHUNK;   // float4 index
    // Tile base is a multiple of 256 -> (i,j) of idx tile_base+tid+256k equals
    // (tid>>2, tid&3) for all k: u is invariant. Input elem = base/4 + tid/4 + 64k.
    const float* ibase = in + (chunk_base >> 2) + (tid >> 2);

    for (int t = 0; t < TILES_PER_BLOCK; ++t) {
        const int b = t & 1;

        // Throttle: before refilling buffer b, the bulk store issued from it
        // (tile t-2) must have finished READING smem.
        if (t >= 2 && tid == 0)
            asm volatile("cp.async.bulk.wait_group.read 1;" ::: "memory");
        __syncthreads();

        // ---- fill tile: 4 independent broadcast loads, 4 STS.128 ----
        const float* ip = ibase + t * (TILE / 4);
        float x0 = __ldg(ip + 0 * 64);
        float x1 = __ldg(ip + 1 * 64);
        float x2 = __ldg(ip + 2 * 64);
        float x3 = __ldg(ip + 3 * 64);
        buf[b][tid + 0 * 256] = make_float4(x0 * u.x, x0 * u.y, x0 * u.z, x0 * u.w);
        buf[b][tid + 1 * 256] = make_float4(x1 * u.x, x1 * u.y, x1 * u.z, x1 * u.w);
        buf[b][tid + 2 * 256] = make_float4(x2 * u.x, x2 * u.y, x2 * u.z, x2 * u.w);
        buf[b][tid + 3 * 256] = make_float4(x3 * u.x, x3 * u.y, x3 * u.z, x3 * u.w);
        __syncthreads();

        // ---- elected thread hands the 16 KiB tile to the async proxy ----
        if (tid == 0) {
            asm volatile("fence.proxy.async.shared::cta;" ::: "memory");
            const float4* gdst = out + chunk_base + (unsigned)t * TILE;
            uint32_t ssrc = smem_u32(&buf[b][0]);
            asm volatile(
                "cp.async.bulk.global.shared::cta.bulk_group [%0], [%1], %2;"
                :: "l"(gdst), "r"(ssrc), "n"(TILE * 16) : "memory");
            asm volatile("cp.async.bulk.commit_group;" ::: "memory");
        }
    }

    // Drain all pending bulk stores before exit.
    if (tid == 0)
        asm volatile("cp.async.bulk.wait_group 0;" ::: "memory");
}

extern "C" void kernel_launch(void* const* d_in, const int* in_sizes, int n_in,
                              void* d_out, int out_size) {
    const float* inputs = (const float*)d_in[0];  // 8*128*128*64 = 8388608
    const float* beta   = (const float*)d_in[1];  // 64*16 = 1024
    float4* out = (float4*)d_out;

    fused_broadcast_mul_tma<<<BLOCKS, THREADS>>>(inputs, beta, out);
}

// round 9
// speedup vs baseline: 1.1167x; 1.1167x over previous
#include <cuda_runtime.h>

// Problem: inputs [8,128,128,64] f32, beta [64,16] f32
// out[e, c] = inputs[e] * u[e%64, c],  u = beta^2 / rowsum(beta^2)
// out flat: n4 = 2^25 float4s. (i = (g>>2)&63, j = g&3) has period 256 in g;
// grid stride is a multiple of 256 -> per-thread u is loop-invariant.
//
// R9: exact-one-wave persistent grid. 1216 blocks = 152 SMs x 8 resident
// (regs capped at 32 via launch_bounds), so every block runs start-to-finish
// with no ragged tail. Grid sweeps output in dense 19 MB windows (the access
// pattern that benchmarked best). 107 full strides + 1 predicated stride.

#define D_DIM 64
#define BLOCKS 1216
#define THREADS 256
#define STRIDE (BLOCKS * THREADS)          // 311296 float4s per grid step
#define FULL_ITERS 107                     // floor(2^25 / STRIDE)
// remainder: 2^25 - 107*STRIDE = 245760 = 960*256 -> blocks < 960 do one extra
#define EXTRA_BLOCKS 960

__global__ void __launch_bounds__(THREADS, 8) fused_broadcast_mul(
    const float* __restrict__ in, const float* __restrict__ beta,
    float4* __restrict__ out) {
    unsigned int g = blockIdx.x * THREADS + threadIdx.x;
    const unsigned int i = (g >> 2) & (D_DIM - 1);  // beta row
    const unsigned int j = g & 3u;                  // float4 quarter of the row

    // ---- one-time prologue: this thread's u quarter, in registers ----
    const float4* br = reinterpret_cast<const float4*>(beta) + i * 4;
    float4 q0 = __ldg(br + 0);
    float4 q1 = __ldg(br + 1);
    float4 q2 = __ldg(br + 2);
    float4 q3 = __ldg(br + 3);
    float s = q0.x * q0.x + q0.y * q0.y + q0.z * q0.z + q0.w * q0.w
            + q1.x * q1.x + q1.y * q1.y + q1.z * q1.z + q1.w * q1.w
            + q2.x * q2.x + q2.y * q2.y + q2.z * q2.z + q2.w * q2.w
            + q3.x * q3.x + q3.y * q3.y + q3.z * q3.z + q3.w * q3.w;
    float inv = 1.0f / s;
    float4 bq = (j == 0) ? q0 : (j == 1) ? q1 : (j == 2) ? q2 : q3;
    const float4 u = make_float4(bq.x * bq.x * inv, bq.y * bq.y * inv,
                                 bq.z * bq.z * inv, bq.w * bq.w * inv);

    // ---- dense-window sweep: interleaved LDG/FMUL/STG, ptxas-pipelined ----
    const float* ip = in + (g >> 2);
    float4* op = out + g;

#pragma unroll 8
    for (int it = 0; it < FULL_ITERS; ++it) {
        float x = __ldg(ip);
        __stcs(op, make_float4(x * u.x, x * u.y, x * u.z, x * u.w));
        ip += STRIDE / 4;
        op += STRIDE;
    }

    // Remainder stride: uniform predicate per block (no divergence).
    if (blockIdx.x < EXTRA_BLOCKS) {
        float x = __ldg(ip);
        __stcs(op, make_float4(x * u.x, x * u.y, x * u.z, x * u.w));
    }
}

extern "C" void kernel_launch(void* const* d_in, const int* in_sizes, int n_in,
                              void* d_out, int out_size) {
    const float* inputs = (const float*)d_in[0];  // 8*128*128*64 = 8388608
    const float* beta   = (const float*)d_in[1];  // 64*16 = 1024
    float4* out = (float4*)d_out;

    fused_broadcast_mul<<<BLOCKS, THREADS>>>(inputs, beta, out);
}